// round 10
// baseline (speedup 1.0000x reference)
#include <cuda_runtime.h>
#include <cuda_bf16.h>
#include <cuda_fp16.h>
#include <cstdint>

#define BB 2
#define CC 64
#define C8 8
#define NN 9216   // 96*96
#define L2E 1.4426950408889634f
#define VSCALE8 1048576.0f   // 2^20, pow2 -> exact unscale

// ---- scratch (static device globals; no allocation at runtime) ----
__device__ float g_q[BB][C8][NN];            // pre-scaled by log2(e)
__device__ float g_k[BB][C8][NN];
__device__ float g_v[BB][CC][NN];
__device__ float g_Zp[BB][2][NN];            // partial Z per i-half
__device__ uint8_t g_vp8[BB][CC][NN];        // v' = v * rZ * 2^20  (e4m3)
__device__ float g_opart[4][BB][CC][NN];     // partial outputs per j-quarter

// ---------------------------------------------------------------------------
// helpers
// ---------------------------------------------------------------------------
__device__ __forceinline__ uint32_t pack_f16x2(float lo, float hi) {
    uint32_t r;
    asm("cvt.rn.f16x2.f32 %0, %1, %2;" : "=r"(r) : "f"(hi), "f"(lo));
    return r;
}

__device__ __forceinline__ uint32_t ex2_h2(uint32_t h) {
    uint32_t r;
    asm("ex2.approx.f16x2 %0, %1;" : "=r"(r) : "r"(h));
    return r;
}

__device__ __forceinline__ uint32_t f16x2_to_e4m3x2(uint32_t h) {
    uint16_t r;
    asm("cvt.rn.satfinite.e4m3x2.f16x2 %0, %1;" : "=h"(r) : "r"(h));
    return (uint32_t)r;
}

__device__ __forceinline__ void mma_tf32(float c[4],
                                         uint32_t a0, uint32_t a1, uint32_t a2, uint32_t a3,
                                         uint32_t b0, uint32_t b1) {
    asm volatile(
        "mma.sync.aligned.m16n8k8.row.col.f32.tf32.tf32.f32 "
        "{%0,%1,%2,%3}, {%4,%5,%6,%7}, {%8,%9}, {%0,%1,%2,%3};"
        : "+f"(c[0]), "+f"(c[1]), "+f"(c[2]), "+f"(c[3])
        : "r"(a0), "r"(a1), "r"(a2), "r"(a3), "r"(b0), "r"(b1));
}

__device__ __forceinline__ void mma_fp8(float c[4],
                                        uint32_t a0, uint32_t a1, uint32_t a2, uint32_t a3,
                                        uint32_t b0, uint32_t b1) {
    asm volatile(
        "mma.sync.aligned.m16n8k32.row.col.f32.e4m3.e4m3.f32 "
        "{%0,%1,%2,%3}, {%4,%5,%6,%7}, {%8,%9}, {%0,%1,%2,%3};"
        : "+f"(c[0]), "+f"(c[1]), "+f"(c[2]), "+f"(c[3])
        : "r"(a0), "r"(a1), "r"(a2), "r"(a3), "r"(b0), "r"(b1));
}

// ============================================================================
// Kernel 1: 1x1-conv projections, 5 groups of 16 output rows.
// ============================================================================
__global__ void __launch_bounds__(128) qkv_kernel(
    const float* __restrict__ x,
    const float* __restrict__ wq, const float* __restrict__ bq,
    const float* __restrict__ wk, const float* __restrict__ bk,
    const float* __restrict__ wv, const float* __restrict__ bv)
{
    __shared__ float sw[16][CC];
    __shared__ float sb[16];
    const int g = blockIdx.y;
    const int b = blockIdx.z;
    const int tid = threadIdx.x;

    for (int idx = tid; idx < 16 * CC; idx += 128) {
        const int row = idx >> 6, c = idx & 63;
        float val;
        if (g == 0) val = (row < 8) ? wq[row * CC + c] * L2E : wk[(row - 8) * CC + c];
        else        val = wv[(16 * (g - 1) + row) * CC + c];
        sw[row][c] = val;
    }
    if (tid < 16) {
        float bval;
        if (g == 0) bval = (tid < 8) ? bq[tid] * L2E : bk[tid - 8];
        else        bval = bv[16 * (g - 1) + tid];
        sb[tid] = bval;
    }
    __syncthreads();

    const int n0 = blockIdx.x * 256 + tid * 2;
    float2 acc[16];
    #pragma unroll
    for (int o = 0; o < 16; o++) { acc[o].x = sb[o]; acc[o].y = sb[o]; }
    const float* xb = x + (size_t)b * CC * NN;
    #pragma unroll 4
    for (int c = 0; c < CC; c++) {
        const float2 xv = *(const float2*)&xb[c * NN + n0];
        #pragma unroll
        for (int o = 0; o < 16; o++) {
            acc[o].x += sw[o][c] * xv.x;
            acc[o].y += sw[o][c] * xv.y;
        }
    }
    if (g == 0) {
        #pragma unroll
        for (int o = 0; o < 8; o++)  *(float2*)&g_q[b][o][n0] = acc[o];
        #pragma unroll
        for (int o = 0; o < 8; o++)  *(float2*)&g_k[b][o][n0] = acc[o + 8];
    } else {
        const int r0 = 16 * (g - 1);
        #pragma unroll
        for (int o = 0; o < 16; o++) *(float2*)&g_v[b][r0 + o][n0] = acc[o];
    }
}

// ============================================================================
// zpass: Zp[b][ihalf][j] = sum over i-half of 2^(q_j . k_i)  (unchanged R9)
// ============================================================================
__global__ void __launch_bounds__(256) zpass_kernel()
{
    __shared__ float skT[2][8 * 136];
    __shared__ float szw[8][128];

    const int b = blockIdx.z;
    const int ihalf = blockIdx.y;
    const int j_base = blockIdx.x * 128;
    const int tid = threadIdx.x;
    const int warp = tid >> 5, lane = tid & 31;
    const int gp = lane >> 2, tg = lane & 3;
    const int iw = warp * 16;

    uint32_t Bq0[16], Bq1[16];
    #pragma unroll
    for (int nt = 0; nt < 16; nt++) {
        const int j = j_base + nt * 8 + gp;
        Bq0[nt] = __float_as_uint(g_q[b][tg][j]);
        Bq1[nt] = __float_as_uint(g_q[b][tg + 4][j]);
    }

    float zacc[32];
    #pragma unroll
    for (int m = 0; m < 32; m++) zacc[m] = 0.f;

    int so[4], si[4];
    #pragma unroll
    for (int t = 0; t < 4; t++) {
        const int e = tid + t * 256;
        so[t] = e >> 7; si[t] = e & 127;
    }

    const int i0h = ihalf * (NN / 2);
    const int NI = NN / 2 / 128;   // 36

    float pre[4];
    #pragma unroll
    for (int t = 0; t < 4; t++) pre[t] = g_k[b][so[t]][i0h + si[t]];
    #pragma unroll
    for (int t = 0; t < 4; t++) skT[0][so[t] * 136 + si[t]] = pre[t];
    __syncthreads();

    for (int it = 0; it < NI; it++) {
        if (it + 1 < NI) {
            const int ib = i0h + (it + 1) * 128;
            #pragma unroll
            for (int t = 0; t < 4; t++) pre[t] = g_k[b][so[t]][ib + si[t]];
        }
        const float* buf = skT[it & 1];
        const uint32_t a0 = __float_as_uint(buf[tg * 136 + iw + gp]);
        const uint32_t a1 = __float_as_uint(buf[tg * 136 + iw + gp + 8]);
        const uint32_t a2 = __float_as_uint(buf[(tg + 4) * 136 + iw + gp]);
        const uint32_t a3 = __float_as_uint(buf[(tg + 4) * 136 + iw + gp + 8]);

        #pragma unroll
        for (int nt = 0; nt < 16; nt++) {
            float e[4] = {0.f, 0.f, 0.f, 0.f};
            mma_tf32(e, a0, a1, a2, a3, Bq0[nt], Bq1[nt]);
            uint32_t h01 = ex2_h2(pack_f16x2(e[0], e[1]));
            uint32_t h23 = ex2_h2(pack_f16x2(e[2], e[3]));
            const float2 f01 = __half22float2(*reinterpret_cast<__half2*>(&h01));
            const float2 f23 = __half22float2(*reinterpret_cast<__half2*>(&h23));
            zacc[2 * nt]     += f01.x + f23.x;
            zacc[2 * nt + 1] += f01.y + f23.y;
        }

        if (it + 1 < NI) {
            float* nbuf = skT[(it + 1) & 1];
            #pragma unroll
            for (int t = 0; t < 4; t++) nbuf[so[t] * 136 + si[t]] = pre[t];
            __syncthreads();
        }
    }

    #pragma unroll
    for (int m = 0; m < 32; m++) {
        float v = zacc[m];
        v += __shfl_xor_sync(~0u, v, 4);
        v += __shfl_xor_sync(~0u, v, 8);
        v += __shfl_xor_sync(~0u, v, 16);
        zacc[m] = v;
    }
    if (gp == 0) {
        #pragma unroll
        for (int m = 0; m < 32; m++) {
            const int jl = (m >> 1) * 8 + 2 * tg + (m & 1);
            szw[warp][jl] = zacc[m];
        }
    }
    __syncthreads();
    if (tid < 128) {
        float z = 0.f;
        #pragma unroll
        for (int w = 0; w < 8; w++) z += szw[w][tid];
        g_Zp[b][ihalf][j_base + tid] = z;
    }
}

// ============================================================================
// vprime: rZ = 1/(Zp0+Zp1);  v'[c][j] = e4m3(v[c][j] * rZ[j] * 2^20)
// 4 j per thread, uint32 packed stores.
// ============================================================================
__global__ void __launch_bounds__(256) vprime_kernel()
{
    const int b = blockIdx.y;
    const int j4 = (blockIdx.x * 256 + threadIdx.x) * 4;
    const float4 z0 = *(const float4*)&g_Zp[b][0][j4];
    const float4 z1 = *(const float4*)&g_Zp[b][1][j4];
    const float r0 = VSCALE8 / (z0.x + z1.x);
    const float r1 = VSCALE8 / (z0.y + z1.y);
    const float r2 = VSCALE8 / (z0.z + z1.z);
    const float r3 = VSCALE8 / (z0.w + z1.w);
    #pragma unroll 8
    for (int c = 0; c < CC; c++) {
        const float4 v = *(const float4*)&g_v[b][c][j4];
        uint16_t lo, hi;
        asm("cvt.rn.satfinite.e4m3x2.f32 %0, %1, %2;" : "=h"(lo) : "f"(v.y * r1), "f"(v.x * r0));
        asm("cvt.rn.satfinite.e4m3x2.f32 %0, %1, %2;" : "=h"(hi) : "f"(v.w * r3), "f"(v.z * r2));
        *(uint32_t*)&g_vp8[b][c][j4] = (uint32_t)lo | ((uint32_t)hi << 16);
    }
}

// ============================================================================
// outpass: fp8 m16n8k32 mma. Energy B-loads use permuted columns sigma so the
// exp'd accumulator pairs land as consecutive-j fp8 A-fragment bytes (k==j
// identity); V' (e4m3) B-fragments are plain LDS.32, no permutation needed.
// grid (36, 4, BB), block 256, m=32/warp.
// ============================================================================
#define SQP 264    // f32 pitch for sq
#define SVP8 272   // byte pitch for sv (mod 128 == 16 -> conflict-free rows)

__device__ __forceinline__ void build_pfrag(
    const float* sq, int sqo0, int sqo1, int jj, int s1,
    const uint32_t (&ak)[2][4], uint32_t (&pa)[2][4])
{
    #pragma unroll
    for (int half = 0; half < 2; half++) {
        const int jb16 = jj + half * 16;
        const uint32_t B0a = __float_as_uint(sq[sqo0 + jb16 + s1]);
        const uint32_t B1a = __float_as_uint(sq[sqo1 + jb16 + s1]);
        const uint32_t B0b = __float_as_uint(sq[sqo0 + jb16 + s1 + 2]);
        const uint32_t B1b = __float_as_uint(sq[sqo1 + jb16 + s1 + 2]);
        #pragma unroll
        for (int h = 0; h < 2; h++) {
            float eA[4] = {0.f, 0.f, 0.f, 0.f};
            float eB[4] = {0.f, 0.f, 0.f, 0.f};
            mma_tf32(eA, ak[h][0], ak[h][1], ak[h][2], ak[h][3], B0a, B1a);
            mma_tf32(eB, ak[h][0], ak[h][1], ak[h][2], ak[h][3], B0b, B1b);
            // rows gp: j = 4tg..4tg+3 (A gives 4tg,4tg+1; B gives 4tg+2,4tg+3)
            const uint32_t cA0 = f16x2_to_e4m3x2(ex2_h2(pack_f16x2(eA[0], eA[1])));
            const uint32_t cB0 = f16x2_to_e4m3x2(ex2_h2(pack_f16x2(eB[0], eB[1])));
            // rows gp+8
            const uint32_t cA1 = f16x2_to_e4m3x2(ex2_h2(pack_f16x2(eA[2], eA[3])));
            const uint32_t cB1 = f16x2_to_e4m3x2(ex2_h2(pack_f16x2(eB[2], eB[3])));
            pa[h][0 + half * 2] = cA0 | (cB0 << 16);
            pa[h][1 + half * 2] = cA1 | (cB1 << 16);
        }
    }
}

__global__ void __launch_bounds__(256, 2) outpass_kernel()
{
    extern __shared__ float sm[];
    float* sq = sm;                              // [8][SQP] f32
    uint8_t* sv = (uint8_t*)(sm + 8 * SQP);      // [64][SVP8] e4m3
    float* strans = sm;                          // epilogue overlay [64][264]

    const int b = blockIdx.z;
    const int jq = blockIdx.y;
    const int i_base = blockIdx.x * 256;
    const int tid = threadIdx.x;
    const int warp = tid >> 5, lane = tid & 31;
    const int gp = lane >> 2, tg = lane & 3;
    const int iw = warp * 32;

    // persistent K-tile A-fragments (raw f32 bits), two m16 halves
    uint32_t ak[2][4];
    #pragma unroll
    for (int h = 0; h < 2; h++) {
        const int ib = i_base + iw + h * 16;
        ak[h][0] = __float_as_uint(g_k[b][tg][ib + gp]);
        ak[h][1] = __float_as_uint(g_k[b][tg][ib + gp + 8]);
        ak[h][2] = __float_as_uint(g_k[b][tg + 4][ib + gp]);
        ak[h][3] = __float_as_uint(g_k[b][tg + 4][ib + gp + 8]);
    }

    float acc[2][8][4];
    #pragma unroll
    for (int h = 0; h < 2; h++)
        #pragma unroll
        for (int nc = 0; nc < 8; nc++)
            #pragma unroll
            for (int s = 0; s < 4; s++) acc[h][nc][s] = 0.f;

    // sigma: output col c of the energy mma must carry j = sigma(c)
    const int s1 = ((gp & 6) << 1) | (gp & 1);
    const int sqo0 = tg * SQP;
    const int sqo1 = (tg + 4) * SQP;
    const int vb0 = gp * SVP8 + 4 * tg;   // V B-frag base (bytes)

    const int j0q = jq * (NN / 4);
    for (int sc = 0; sc < NN / 4 / 256; sc++) {
        const int jb = j0q + sc * 256;
        __syncthreads();
        #pragma unroll
        for (int t = 0; t < 2; t++) {
            const int idx = tid + t * 256;
            const int o = idx >> 6, c4 = idx & 63;
            *(float4*)&sq[o * SQP + c4 * 4] = *(const float4*)&g_q[b][o][jb + c4 * 4];
        }
        #pragma unroll
        for (int t = 0; t < 4; t++) {
            const int idx = tid + t * 256;
            const int row = idx >> 4, sg = idx & 15;
            *(uint4*)&sv[row * SVP8 + sg * 16] = *(const uint4*)&g_vp8[b][row][jb + sg * 16];
        }
        __syncthreads();

        uint32_t pac[2][4], pan[2][4];
        build_pfrag(sq, sqo0, sqo1, 0, s1, ak, pac);

        #pragma unroll 2
        for (int t = 0; t < 8; t++) {
            const int jj = t * 32;
            if (t + 1 < 8) build_pfrag(sq, sqo0, sqo1, jj + 32, s1, ak, pan);
            #pragma unroll
            for (int nc = 0; nc < 8; nc++) {
                const int vbase = vb0 + nc * 8 * SVP8 + jj;
                const uint32_t b0 = *(const uint32_t*)&sv[vbase];
                const uint32_t b1 = *(const uint32_t*)&sv[vbase + 16];
                mma_fp8(acc[0][nc], pac[0][0], pac[0][1], pac[0][2], pac[0][3], b0, b1);
                mma_fp8(acc[1][nc], pac[1][0], pac[1][1], pac[1][2], pac[1][3], b0, b1);
            }
            if (t + 1 < 8) {
                #pragma unroll
                for (int h = 0; h < 2; h++)
                    #pragma unroll
                    for (int s = 0; s < 4; s++) pac[h][s] = pan[h][s];
            }
        }
    }

    // epilogue: transpose [i][c] -> [c][i] via smem overlay, coalesced write
    __syncthreads();
    #pragma unroll
    for (int h = 0; h < 2; h++) {
        const int il = iw + h * 16;
        #pragma unroll
        for (int nc = 0; nc < 8; nc++) {
            strans[(nc * 8 + 2 * tg) * 264 + il + gp]         = acc[h][nc][0];
            strans[(nc * 8 + 2 * tg + 1) * 264 + il + gp]     = acc[h][nc][1];
            strans[(nc * 8 + 2 * tg) * 264 + il + gp + 8]     = acc[h][nc][2];
            strans[(nc * 8 + 2 * tg + 1) * 264 + il + gp + 8] = acc[h][nc][3];
        }
    }
    __syncthreads();
    #pragma unroll
    for (int t = 0; t < 16; t++) {
        const int idx = tid + t * 256;
        const int c = idx >> 6, f4 = idx & 63;
        const float4 v = *(const float4*)&strans[c * 264 + f4 * 4];
        *(float4*)&g_opart[jq][b][c][i_base + f4 * 4] = v;
    }
}

// ============================================================================
// combine: out = (gamma/2^20)*(op0+op1+op2+op3) + x  (fixed order)
// ============================================================================
__global__ void __launch_bounds__(256) combine_kernel(
    const float* __restrict__ x,
    const float* __restrict__ gamma,
    float* __restrict__ out)
{
    const int b = blockIdx.y;
    const size_t idx = ((size_t)blockIdx.x * 256 + threadIdx.x) * 4;
    const float gma = gamma[0] * (1.0f / VSCALE8);
    const float4 p0 = *(const float4*)&g_opart[0][b][0][idx];
    const float4 p1 = *(const float4*)&g_opart[1][b][0][idx];
    const float4 p2 = *(const float4*)&g_opart[2][b][0][idx];
    const float4 p3 = *(const float4*)&g_opart[3][b][0][idx];
    const float4 xv = *(const float4*)&x[(size_t)b * CC * NN + idx];
    float4 o;
    o.x = gma * ((p0.x + p1.x) + (p2.x + p3.x)) + xv.x;
    o.y = gma * ((p0.y + p1.y) + (p2.y + p3.y)) + xv.y;
    o.z = gma * ((p0.z + p1.z) + (p2.z + p3.z)) + xv.z;
    o.w = gma * ((p0.w + p1.w) + (p2.w + p3.w)) + xv.w;
    *(float4*)&out[(size_t)b * CC * NN + idx] = o;
}

// ============================================================================
extern "C" void kernel_launch(void* const* d_in, const int* in_sizes, int n_in,
                              void* d_out, int out_size)
{
    const float* x     = (const float*)d_in[0];
    const float* wq    = (const float*)d_in[1];
    const float* bq    = (const float*)d_in[2];
    const float* wk    = (const float*)d_in[3];
    const float* bk    = (const float*)d_in[4];
    const float* wv    = (const float*)d_in[5];
    const float* bv    = (const float*)d_in[6];
    const float* gamma = (const float*)d_in[7];
    float* out = (float*)d_out;

    {
        dim3 grid(NN / 256, 5, BB);
        qkv_kernel<<<grid, 128>>>(x, wq, bq, wk, bk, wv, bv);
    }
    {
        dim3 grid(NN / 128, 2, BB);
        zpass_kernel<<<grid, 256>>>();
    }
    {
        dim3 grid(NN / 1024, BB);
        vprime_kernel<<<grid, 256>>>();
    }
    {
        const size_t stage_bytes = 8 * SQP * sizeof(float) + 64 * SVP8;
        const size_t trans_bytes = 64 * 264 * sizeof(float);
        const size_t shmem = stage_bytes > trans_bytes ? stage_bytes : trans_bytes;
        cudaFuncSetAttribute(outpass_kernel,
                             cudaFuncAttributeMaxDynamicSharedMemorySize, (int)shmem);
        dim3 grid(NN / 256, 4, BB);
        outpass_kernel<<<grid, 256, shmem>>>();
    }
    {
        dim3 grid(CC * NN / 4 / 256, BB);
        combine_kernel<<<grid, 256>>>(x, gamma, out);
    }
}

// round 11
// speedup vs baseline: 1.2154x; 1.2154x over previous
#include <cuda_runtime.h>
#include <cuda_bf16.h>
#include <cuda_fp16.h>
#include <cstdint>

#define BB 2
#define CC 64
#define C8 8
#define NN 9216   // 96*96
#define L2E 1.4426950408889634f
#define VSCALE 4096.0f     // 2^12, pow2 -> exact unscale

// ---- scratch (static device globals; no allocation at runtime) ----
__device__ float g_q[BB][C8][NN];            // pre-scaled by log2(e)
__device__ float g_k[BB][C8][NN];
__device__ float g_v[BB][CC][NN];
__device__ float g_Zp[BB][2][NN];            // partial Z per i-half
__device__ __half g_vp[BB][CC][NN];          // v' = v * rZ * 2^12  (fp16)
__device__ float g_opart[4][BB][CC][NN];     // partial outputs per j-quarter

// ---------------------------------------------------------------------------
// helpers
// ---------------------------------------------------------------------------
__device__ __forceinline__ uint32_t pack_f16x2(float lo, float hi) {
    uint32_t r;
    asm("cvt.rn.f16x2.f32 %0, %1, %2;" : "=r"(r) : "f"(hi), "f"(lo));
    return r;
}

__device__ __forceinline__ uint32_t ex2_h2(uint32_t h) {
    uint32_t r;
    asm("ex2.approx.f16x2 %0, %1;" : "=r"(r) : "r"(h));
    return r;
}

__device__ __forceinline__ uint32_t hadd2(uint32_t a, uint32_t b) {
    uint32_t r;
    asm("add.rn.f16x2 %0, %1, %2;" : "=r"(r) : "r"(a), "r"(b));
    return r;
}

__device__ __forceinline__ void mma_tf32(float c[4],
                                         uint32_t a0, uint32_t a1, uint32_t a2, uint32_t a3,
                                         uint32_t b0, uint32_t b1) {
    asm volatile(
        "mma.sync.aligned.m16n8k8.row.col.f32.tf32.tf32.f32 "
        "{%0,%1,%2,%3}, {%4,%5,%6,%7}, {%8,%9}, {%0,%1,%2,%3};"
        : "+f"(c[0]), "+f"(c[1]), "+f"(c[2]), "+f"(c[3])
        : "r"(a0), "r"(a1), "r"(a2), "r"(a3), "r"(b0), "r"(b1));
}

__device__ __forceinline__ void mma_f16(float c[4],
                                        uint32_t a0, uint32_t a1, uint32_t a2, uint32_t a3,
                                        uint32_t b0, uint32_t b1) {
    asm volatile(
        "mma.sync.aligned.m16n8k16.row.col.f32.f16.f16.f32 "
        "{%0,%1,%2,%3}, {%4,%5,%6,%7}, {%8,%9}, {%0,%1,%2,%3};"
        : "+f"(c[0]), "+f"(c[1]), "+f"(c[2]), "+f"(c[3])
        : "r"(a0), "r"(a1), "r"(a2), "r"(a3), "r"(b0), "r"(b1));
}

__device__ __forceinline__ void ldsm_x4(uint32_t& r0, uint32_t& r1,
                                        uint32_t& r2, uint32_t& r3, uint32_t addr) {
    asm volatile("ldmatrix.sync.aligned.m8n8.x4.shared.b16 {%0,%1,%2,%3}, [%4];"
                 : "=r"(r0), "=r"(r1), "=r"(r2), "=r"(r3) : "r"(addr));
}

// ============================================================================
// Kernel 1: 1x1-conv projections, 5 groups of 16 output rows.
// ============================================================================
__global__ void __launch_bounds__(128) qkv_kernel(
    const float* __restrict__ x,
    const float* __restrict__ wq, const float* __restrict__ bq,
    const float* __restrict__ wk, const float* __restrict__ bk,
    const float* __restrict__ wv, const float* __restrict__ bv)
{
    __shared__ float sw[16][CC];
    __shared__ float sb[16];
    const int g = blockIdx.y;
    const int b = blockIdx.z;
    const int tid = threadIdx.x;

    for (int idx = tid; idx < 16 * CC; idx += 128) {
        const int row = idx >> 6, c = idx & 63;
        float val;
        if (g == 0) val = (row < 8) ? wq[row * CC + c] * L2E : wk[(row - 8) * CC + c];
        else        val = wv[(16 * (g - 1) + row) * CC + c];
        sw[row][c] = val;
    }
    if (tid < 16) {
        float bval;
        if (g == 0) bval = (tid < 8) ? bq[tid] * L2E : bk[tid - 8];
        else        bval = bv[16 * (g - 1) + tid];
        sb[tid] = bval;
    }
    __syncthreads();

    const int n0 = blockIdx.x * 256 + tid * 2;
    float2 acc[16];
    #pragma unroll
    for (int o = 0; o < 16; o++) { acc[o].x = sb[o]; acc[o].y = sb[o]; }
    const float* xb = x + (size_t)b * CC * NN;
    #pragma unroll 4
    for (int c = 0; c < CC; c++) {
        const float2 xv = *(const float2*)&xb[c * NN + n0];
        #pragma unroll
        for (int o = 0; o < 16; o++) {
            acc[o].x += sw[o][c] * xv.x;
            acc[o].y += sw[o][c] * xv.y;
        }
    }
    if (g == 0) {
        #pragma unroll
        for (int o = 0; o < 8; o++)  *(float2*)&g_q[b][o][n0] = acc[o];
        #pragma unroll
        for (int o = 0; o < 8; o++)  *(float2*)&g_k[b][o][n0] = acc[o + 8];
    } else {
        const int r0 = 16 * (g - 1);
        #pragma unroll
        for (int o = 0; o < 16; o++) *(float2*)&g_v[b][r0 + o][n0] = acc[o];
    }
}

// ============================================================================
// zpass: Zp[b][ihalf][j] = sum over i-half of 2^(q_j . k_i)   (q log2e-scaled)
// grid (72, 2, BB), block 256. ex2 in f16x2; accumulation also in f16x2
// (add.rn.f16x2): slot sums <= ~600 << 65504, rounding ~0.1% random which
// averages out over the 64-way i-reduction (rZ err ~3e-4 -> ~1e-5 on output).
// ============================================================================
__global__ void __launch_bounds__(256) zpass_kernel()
{
    __shared__ float skT[2][8 * 136];
    __shared__ float szw[8][128];

    const int b = blockIdx.z;
    const int ihalf = blockIdx.y;
    const int j_base = blockIdx.x * 128;
    const int tid = threadIdx.x;
    const int warp = tid >> 5, lane = tid & 31;
    const int gp = lane >> 2, tg = lane & 3;
    const int iw = warp * 16;

    uint32_t Bq0[16], Bq1[16];
    #pragma unroll
    for (int nt = 0; nt < 16; nt++) {
        const int j = j_base + nt * 8 + gp;
        Bq0[nt] = __float_as_uint(g_q[b][tg][j]);
        Bq1[nt] = __float_as_uint(g_q[b][tg + 4][j]);
    }

    uint32_t zaccH[16];
    #pragma unroll
    for (int m = 0; m < 16; m++) zaccH[m] = 0u;

    int so[4], si[4];
    #pragma unroll
    for (int t = 0; t < 4; t++) {
        const int e = tid + t * 256;
        so[t] = e >> 7; si[t] = e & 127;
    }

    const int i0h = ihalf * (NN / 2);
    const int NI = NN / 2 / 128;   // 36

    float pre[4];
    #pragma unroll
    for (int t = 0; t < 4; t++) pre[t] = g_k[b][so[t]][i0h + si[t]];
    #pragma unroll
    for (int t = 0; t < 4; t++) skT[0][so[t] * 136 + si[t]] = pre[t];
    __syncthreads();

    for (int it = 0; it < NI; it++) {
        if (it + 1 < NI) {
            const int ib = i0h + (it + 1) * 128;
            #pragma unroll
            for (int t = 0; t < 4; t++) pre[t] = g_k[b][so[t]][ib + si[t]];
        }
        const float* buf = skT[it & 1];
        const uint32_t a0 = __float_as_uint(buf[tg * 136 + iw + gp]);
        const uint32_t a1 = __float_as_uint(buf[tg * 136 + iw + gp + 8]);
        const uint32_t a2 = __float_as_uint(buf[(tg + 4) * 136 + iw + gp]);
        const uint32_t a3 = __float_as_uint(buf[(tg + 4) * 136 + iw + gp + 8]);

        #pragma unroll
        for (int nt = 0; nt < 16; nt++) {
            float e[4] = {0.f, 0.f, 0.f, 0.f};
            mma_tf32(e, a0, a1, a2, a3, Bq0[nt], Bq1[nt]);
            const uint32_t h01 = ex2_h2(pack_f16x2(e[0], e[1]));   // rows gp
            const uint32_t h23 = ex2_h2(pack_f16x2(e[2], e[3]));   // rows gp+8
            zaccH[nt] = hadd2(zaccH[nt], hadd2(h01, h23));
        }

        if (it + 1 < NI) {
            float* nbuf = skT[(it + 1) & 1];
            #pragma unroll
            for (int t = 0; t < 4; t++) nbuf[so[t] * 136 + si[t]] = pre[t];
            __syncthreads();
        }
    }

    // reduce over gp lanes (same tg share same j), still in f16x2
    #pragma unroll
    for (int nt = 0; nt < 16; nt++) {
        uint32_t v = zaccH[nt];
        v = hadd2(v, __shfl_xor_sync(~0u, v, 4));
        v = hadd2(v, __shfl_xor_sync(~0u, v, 8));
        v = hadd2(v, __shfl_xor_sync(~0u, v, 16));
        if (gp == 0) {
            const float2 f = __half22float2(*reinterpret_cast<const __half2*>(&v));
            szw[warp][nt * 8 + 2 * tg]     = f.x;
            szw[warp][nt * 8 + 2 * tg + 1] = f.y;
        }
    }
    __syncthreads();
    if (tid < 128) {
        float z = 0.f;
        #pragma unroll
        for (int w = 0; w < 8; w++) z += szw[w][tid];
        g_Zp[b][ihalf][j_base + tid] = z;
    }
}

// ============================================================================
// vprime: rZ = 1/(Zp0+Zp1);  v'[c][j] = f16(v[c][j] * rZ[j] * 2^12)
// ============================================================================
__global__ void __launch_bounds__(256) vprime_kernel()
{
    const int b = blockIdx.y;
    const int j = blockIdx.x * 256 + threadIdx.x;
    const float rzs = VSCALE / (g_Zp[b][0][j] + g_Zp[b][1][j]);
    #pragma unroll 8
    for (int c = 0; c < CC; c++)
        g_vp[b][c][j] = __float2half(g_v[b][c][j] * rzs);
}

// ============================================================================
// outpass: opart[jq][b][c][i] = sum over j-quarter of v'[c,j]*2^(q_j.k_i)
// grid (36, 4, BB), block 256, m=32/warp, ldmatrix.x4, f16 mma.
// Software-pipelined P fragments; t-loop unroll 4 so the pac<->pan register
// copies are renamed away by ptxas.
// ============================================================================
#define SQP 264   // f32 pitch for sq
#define SVP 264   // f16 pitch for sv

__global__ void __launch_bounds__(256, 2) outpass_kernel()
{
    extern __shared__ float sm[];
    float* sq = sm;                              // [8][SQP] f32
    __half* sv = (__half*)(sm + 8 * SQP);        // [64][SVP]
    float* strans = sm;                          // epilogue overlay [64][264]

    const int b = blockIdx.z;
    const int jq = blockIdx.y;
    const int i_base = blockIdx.x * 256;
    const int tid = threadIdx.x;
    const int warp = tid >> 5, lane = tid & 31;
    const int gp = lane >> 2, tg = lane & 3;
    const int iw = warp * 32;

    // persistent K-tile A-fragments (raw f32 bits), two m16 halves
    uint32_t ak[2][4];
    #pragma unroll
    for (int h = 0; h < 2; h++) {
        const int ib = i_base + iw + h * 16;
        ak[h][0] = __float_as_uint(g_k[b][tg][ib + gp]);
        ak[h][1] = __float_as_uint(g_k[b][tg][ib + gp + 8]);
        ak[h][2] = __float_as_uint(g_k[b][tg + 4][ib + gp]);
        ak[h][3] = __float_as_uint(g_k[b][tg + 4][ib + gp + 8]);
    }

    float acc[2][8][4];
    #pragma unroll
    for (int h = 0; h < 2; h++)
        #pragma unroll
        for (int nc = 0; nc < 8; nc++)
            #pragma unroll
            for (int s = 0; s < 4; s++) acc[h][nc][s] = 0.f;

    uint32_t sv_u32;
    asm("{ .reg .u64 t; cvta.to.shared.u64 t, %1; cvt.u32.u64 %0, t; }"
        : "=r"(sv_u32) : "l"(sv));
    const int mrow = ((lane >> 4) << 3) + (lane & 7);  // ldmatrix row (0..15)
    const int mcol = ((lane >> 3) & 1) * 8;            // j offset 0 or 8

    uint32_t addrp[4];
    #pragma unroll
    for (int p = 0; p < 4; p++)
        addrp[p] = sv_u32 + (uint32_t)(((p * 16 + mrow) * SVP + mcol) * 2);
    const int sqo0 = tg * SQP + gp;
    const int sqo1 = (tg + 4) * SQP + gp;

    const int j0q = jq * (NN / 4);
    for (int sc = 0; sc < NN / 4 / 256; sc++) {
        const int jb = j0q + sc * 256;
        __syncthreads();
        #pragma unroll
        for (int t = 0; t < 2; t++) {
            const int idx = tid + t * 256;
            const int o = idx >> 6, c4 = idx & 63;
            *(float4*)&sq[o * SQP + c4 * 4] = *(const float4*)&g_q[b][o][jb + c4 * 4];
        }
        #pragma unroll
        for (int t = 0; t < 8; t++) {
            const int idx = tid + t * 256;
            const int row = idx >> 5, q8 = idx & 31;
            *(uint4*)&sv[row * SVP + q8 * 8] = *(const uint4*)&g_vp[b][row][jb + q8 * 8];
        }
        __syncthreads();

        // ---- prologue: P fragments for t=0 ----
        uint32_t pac[2][4];
        {
            const uint32_t B0a = __float_as_uint(sq[sqo0]);
            const uint32_t B1a = __float_as_uint(sq[sqo1]);
            const uint32_t B0b = __float_as_uint(sq[sqo0 + 8]);
            const uint32_t B1b = __float_as_uint(sq[sqo1 + 8]);
            #pragma unroll
            for (int h = 0; h < 2; h++) {
                float eA[4] = {0.f, 0.f, 0.f, 0.f};
                float eB[4] = {0.f, 0.f, 0.f, 0.f};
                mma_tf32(eA, ak[h][0], ak[h][1], ak[h][2], ak[h][3], B0a, B1a);
                mma_tf32(eB, ak[h][0], ak[h][1], ak[h][2], ak[h][3], B0b, B1b);
                pac[h][0] = ex2_h2(pack_f16x2(eA[0], eA[1]));
                pac[h][1] = ex2_h2(pack_f16x2(eA[2], eA[3]));
                pac[h][2] = ex2_h2(pack_f16x2(eB[0], eB[1]));
                pac[h][3] = ex2_h2(pack_f16x2(eB[2], eB[3]));
            }
        }

        #pragma unroll 4
        for (int t = 0; t < 16; t++) {
            const int jj = t * 16;
            uint32_t pan[2][4];
            // ---- MUFU stream: P fragments for t+1 ----
            if (t + 1 < 16) {
                const int jn = jj + 16;
                const uint32_t B0a = __float_as_uint(sq[sqo0 + jn]);
                const uint32_t B1a = __float_as_uint(sq[sqo1 + jn]);
                const uint32_t B0b = __float_as_uint(sq[sqo0 + jn + 8]);
                const uint32_t B1b = __float_as_uint(sq[sqo1 + jn + 8]);
                #pragma unroll
                for (int h = 0; h < 2; h++) {
                    float eA[4] = {0.f, 0.f, 0.f, 0.f};
                    float eB[4] = {0.f, 0.f, 0.f, 0.f};
                    mma_tf32(eA, ak[h][0], ak[h][1], ak[h][2], ak[h][3], B0a, B1a);
                    mma_tf32(eB, ak[h][0], ak[h][1], ak[h][2], ak[h][3], B0b, B1b);
                    pan[h][0] = ex2_h2(pack_f16x2(eA[0], eA[1]));
                    pan[h][1] = ex2_h2(pack_f16x2(eA[2], eA[3]));
                    pan[h][2] = ex2_h2(pack_f16x2(eB[0], eB[1]));
                    pan[h][3] = ex2_h2(pack_f16x2(eB[2], eB[3]));
                }
            }
            // ---- tensor stream: mma2 batch for t ----
            #pragma unroll
            for (int p = 0; p < 4; p++) {
                uint32_t r0, r1, r2, r3;
                ldsm_x4(r0, r1, r2, r3, addrp[p] + (uint32_t)(jj * 2));
                #pragma unroll
                for (int h = 0; h < 2; h++) {
                    mma_f16(acc[h][2 * p],     pac[h][0], pac[h][1], pac[h][2], pac[h][3], r0, r1);
                    mma_f16(acc[h][2 * p + 1], pac[h][0], pac[h][1], pac[h][2], pac[h][3], r2, r3);
                }
            }
            if (t + 1 < 16) {
                #pragma unroll
                for (int h = 0; h < 2; h++)
                    #pragma unroll
                    for (int s = 0; s < 4; s++) pac[h][s] = pan[h][s];
            }
        }
    }

    // epilogue: transpose [i][c] -> [c][i] via smem overlay, coalesced write
    __syncthreads();
    #pragma unroll
    for (int h = 0; h < 2; h++) {
        const int il = iw + h * 16;
        #pragma unroll
        for (int nc = 0; nc < 8; nc++) {
            strans[(nc * 8 + 2 * tg) * 264 + il + gp]         = acc[h][nc][0];
            strans[(nc * 8 + 2 * tg + 1) * 264 + il + gp]     = acc[h][nc][1];
            strans[(nc * 8 + 2 * tg) * 264 + il + gp + 8]     = acc[h][nc][2];
            strans[(nc * 8 + 2 * tg + 1) * 264 + il + gp + 8] = acc[h][nc][3];
        }
    }
    __syncthreads();
    #pragma unroll
    for (int t = 0; t < 16; t++) {
        const int idx = tid + t * 256;
        const int c = idx >> 6, f4 = idx & 63;
        const float4 v = *(const float4*)&strans[c * 264 + f4 * 4];
        *(float4*)&g_opart[jq][b][c][i_base + f4 * 4] = v;
    }
}

// ============================================================================
// combine: out = (gamma/2^12)*(op0+op1+op2+op3) + x  (fixed order)
// ============================================================================
__global__ void __launch_bounds__(256) combine_kernel(
    const float* __restrict__ x,
    const float* __restrict__ gamma,
    float* __restrict__ out)
{
    const int b = blockIdx.y;
    const size_t idx = ((size_t)blockIdx.x * 256 + threadIdx.x) * 4;
    const float gma = gamma[0] * (1.0f / VSCALE);
    const float4 p0 = *(const float4*)&g_opart[0][b][0][idx];
    const float4 p1 = *(const float4*)&g_opart[1][b][0][idx];
    const float4 p2 = *(const float4*)&g_opart[2][b][0][idx];
    const float4 p3 = *(const float4*)&g_opart[3][b][0][idx];
    const float4 xv = *(const float4*)&x[(size_t)b * CC * NN + idx];
    float4 o;
    o.x = gma * ((p0.x + p1.x) + (p2.x + p3.x)) + xv.x;
    o.y = gma * ((p0.y + p1.y) + (p2.y + p3.y)) + xv.y;
    o.z = gma * ((p0.z + p1.z) + (p2.z + p3.z)) + xv.z;
    o.w = gma * ((p0.w + p1.w) + (p2.w + p3.w)) + xv.w;
    *(float4*)&out[(size_t)b * CC * NN + idx] = o;
}

// ============================================================================
extern "C" void kernel_launch(void* const* d_in, const int* in_sizes, int n_in,
                              void* d_out, int out_size)
{
    const float* x     = (const float*)d_in[0];
    const float* wq    = (const float*)d_in[1];
    const float* bq    = (const float*)d_in[2];
    const float* wk    = (const float*)d_in[3];
    const float* bk    = (const float*)d_in[4];
    const float* wv    = (const float*)d_in[5];
    const float* bv    = (const float*)d_in[6];
    const float* gamma = (const float*)d_in[7];
    float* out = (float*)d_out;

    {
        dim3 grid(NN / 256, 5, BB);
        qkv_kernel<<<grid, 128>>>(x, wq, bq, wk, bk, wv, bv);
    }
    {
        dim3 grid(NN / 128, 2, BB);
        zpass_kernel<<<grid, 256>>>();
    }
    {
        dim3 grid(NN / 256, BB);
        vprime_kernel<<<grid, 256>>>();
    }
    {
        const size_t stage_bytes = 8 * SQP * sizeof(float) + 64 * SVP * sizeof(__half);
        const size_t trans_bytes = 64 * 264 * sizeof(float);
        const size_t shmem = stage_bytes > trans_bytes ? stage_bytes : trans_bytes;
        cudaFuncSetAttribute(outpass_kernel,
                             cudaFuncAttributeMaxDynamicSharedMemorySize, (int)shmem);
        dim3 grid(NN / 256, 4, BB);
        outpass_kernel<<<grid, 256, shmem>>>();
    }
    {
        dim3 grid(CC * NN / 4 / 256, BB);
        combine_kernel<<<grid, 256>>>(x, gamma, out);
    }
}

// round 13
// speedup vs baseline: 1.3119x; 1.0794x over previous
#include <cuda_runtime.h>
#include <cuda_bf16.h>
#include <cuda_fp16.h>
#include <cstdint>

#define BB 2
#define CC 64
#define C8 8
#define NN 9216   // 96*96
#define L2E 1.4426950408889634f
#define VSCALE 4096.0f     // 2^12, pow2 -> exact unscale

// ---- scratch (static device globals; no allocation at runtime) ----
__device__ float g_q[BB][C8][NN];            // pre-scaled by log2(e)
__device__ float g_k[BB][C8][NN];
__device__ float g_v[BB][CC][NN];
__device__ __half g_vp[BB][CC][NN];          // v' = v * rZ * 2^12  (fp16)
__device__ float g_opart[4][BB][CC][NN];     // partial outputs per j-quarter

// ---------------------------------------------------------------------------
// helpers
// ---------------------------------------------------------------------------
__device__ __forceinline__ uint32_t pack_f16x2(float lo, float hi) {
    uint32_t r;
    asm("cvt.rn.f16x2.f32 %0, %1, %2;" : "=r"(r) : "f"(hi), "f"(lo));
    return r;
}

__device__ __forceinline__ uint32_t ex2_h2(uint32_t h) {
    uint32_t r;
    asm("ex2.approx.f16x2 %0, %1;" : "=r"(r) : "r"(h));
    return r;
}

__device__ __forceinline__ uint32_t hadd2(uint32_t a, uint32_t b) {
    uint32_t r;
    asm("add.rn.f16x2 %0, %1, %2;" : "=r"(r) : "r"(a), "r"(b));
    return r;
}

__device__ __forceinline__ void mma_tf32(float c[4],
                                         uint32_t a0, uint32_t a1, uint32_t a2, uint32_t a3,
                                         uint32_t b0, uint32_t b1) {
    asm volatile(
        "mma.sync.aligned.m16n8k8.row.col.f32.tf32.tf32.f32 "
        "{%0,%1,%2,%3}, {%4,%5,%6,%7}, {%8,%9}, {%0,%1,%2,%3};"
        : "+f"(c[0]), "+f"(c[1]), "+f"(c[2]), "+f"(c[3])
        : "r"(a0), "r"(a1), "r"(a2), "r"(a3), "r"(b0), "r"(b1));
}

__device__ __forceinline__ void mma_f16(float c[4],
                                        uint32_t a0, uint32_t a1, uint32_t a2, uint32_t a3,
                                        uint32_t b0, uint32_t b1) {
    asm volatile(
        "mma.sync.aligned.m16n8k16.row.col.f32.f16.f16.f32 "
        "{%0,%1,%2,%3}, {%4,%5,%6,%7}, {%8,%9}, {%0,%1,%2,%3};"
        : "+f"(c[0]), "+f"(c[1]), "+f"(c[2]), "+f"(c[3])
        : "r"(a0), "r"(a1), "r"(a2), "r"(a3), "r"(b0), "r"(b1));
}

__device__ __forceinline__ void ldsm_x4(uint32_t& r0, uint32_t& r1,
                                        uint32_t& r2, uint32_t& r3, uint32_t addr) {
    asm volatile("ldmatrix.sync.aligned.m8n8.x4.shared.b16 {%0,%1,%2,%3}, [%4];"
                 : "=r"(r0), "=r"(r1), "=r"(r2), "=r"(r3) : "r"(addr));
}

// ============================================================================
// Kernel 1: 1x1-conv projections, 5 groups of 16 output rows.
// ============================================================================
__global__ void __launch_bounds__(128) qkv_kernel(
    const float* __restrict__ x,
    const float* __restrict__ wq, const float* __restrict__ bq,
    const float* __restrict__ wk, const float* __restrict__ bk,
    const float* __restrict__ wv, const float* __restrict__ bv)
{
    __shared__ float sw[16][CC];
    __shared__ float sb[16];
    const int g = blockIdx.y;
    const int b = blockIdx.z;
    const int tid = threadIdx.x;

    for (int idx = tid; idx < 16 * CC; idx += 128) {
        const int row = idx >> 6, c = idx & 63;
        float val;
        if (g == 0) val = (row < 8) ? wq[row * CC + c] * L2E : wk[(row - 8) * CC + c];
        else        val = wv[(16 * (g - 1) + row) * CC + c];
        sw[row][c] = val;
    }
    if (tid < 16) {
        float bval;
        if (g == 0) bval = (tid < 8) ? bq[tid] * L2E : bk[tid - 8];
        else        bval = bv[16 * (g - 1) + tid];
        sb[tid] = bval;
    }
    __syncthreads();

    const int n0 = blockIdx.x * 256 + tid * 2;
    float2 acc[16];
    #pragma unroll
    for (int o = 0; o < 16; o++) { acc[o].x = sb[o]; acc[o].y = sb[o]; }
    const float* xb = x + (size_t)b * CC * NN;
    #pragma unroll 4
    for (int c = 0; c < CC; c++) {
        const float2 xv = *(const float2*)&xb[c * NN + n0];
        #pragma unroll
        for (int o = 0; o < 16; o++) {
            acc[o].x += sw[o][c] * xv.x;
            acc[o].y += sw[o][c] * xv.y;
        }
    }
    if (g == 0) {
        #pragma unroll
        for (int o = 0; o < 8; o++)  *(float2*)&g_q[b][o][n0] = acc[o];
        #pragma unroll
        for (int o = 0; o < 8; o++)  *(float2*)&g_k[b][o][n0] = acc[o + 8];
    } else {
        const int r0 = 16 * (g - 1);
        #pragma unroll
        for (int o = 0; o < 16; o++) *(float2*)&g_v[b][r0 + o][n0] = acc[o];
    }
}

// ============================================================================
// zvpass: fused Z + v'. Block owns 64 j's, sweeps ALL i (72 chunks of 128):
// Z_j computed fully locally -> rZ -> v' slice converted in the same kernel.
// grid (144, BB), block 256, 2 blocks/SM. ex2 + accumulation in f16x2.
// ============================================================================
__global__ void __launch_bounds__(256) zvpass_kernel()
{
    __shared__ float skT[2][8 * 136];
    __shared__ float szw[8][64];
    __shared__ float srz[64];

    const int b = blockIdx.y;
    const int j_base = blockIdx.x * 64;
    const int tid = threadIdx.x;
    const int warp = tid >> 5, lane = tid & 31;
    const int gp = lane >> 2, tg = lane & 3;
    const int iw = warp * 16;

    // persistent q B-fragments: 8 n8 j-tiles
    uint32_t Bq0[8], Bq1[8];
    #pragma unroll
    for (int nt = 0; nt < 8; nt++) {
        const int j = j_base + nt * 8 + gp;
        Bq0[nt] = __float_as_uint(g_q[b][tg][j]);
        Bq1[nt] = __float_as_uint(g_q[b][tg + 4][j]);
    }

    uint32_t zaccH[8];
    #pragma unroll
    for (int m = 0; m < 8; m++) zaccH[m] = 0u;

    int so[4], si[4];
    #pragma unroll
    for (int t = 0; t < 4; t++) {
        const int e = tid + t * 256;
        so[t] = e >> 7; si[t] = e & 127;
    }

    const int NI = NN / 128;   // 72

    float pre[4];
    #pragma unroll
    for (int t = 0; t < 4; t++) pre[t] = g_k[b][so[t]][si[t]];
    #pragma unroll
    for (int t = 0; t < 4; t++) skT[0][so[t] * 136 + si[t]] = pre[t];
    __syncthreads();

    for (int it = 0; it < NI; it++) {
        if (it + 1 < NI) {
            const int ib = (it + 1) * 128;
            #pragma unroll
            for (int t = 0; t < 4; t++) pre[t] = g_k[b][so[t]][ib + si[t]];
        }
        const float* buf = skT[it & 1];
        const uint32_t a0 = __float_as_uint(buf[tg * 136 + iw + gp]);
        const uint32_t a1 = __float_as_uint(buf[tg * 136 + iw + gp + 8]);
        const uint32_t a2 = __float_as_uint(buf[(tg + 4) * 136 + iw + gp]);
        const uint32_t a3 = __float_as_uint(buf[(tg + 4) * 136 + iw + gp + 8]);

        #pragma unroll
        for (int nt = 0; nt < 8; nt++) {
            float e[4] = {0.f, 0.f, 0.f, 0.f};
            mma_tf32(e, a0, a1, a2, a3, Bq0[nt], Bq1[nt]);
            const uint32_t h01 = ex2_h2(pack_f16x2(e[0], e[1]));   // rows gp
            const uint32_t h23 = ex2_h2(pack_f16x2(e[2], e[3]));   // rows gp+8
            zaccH[nt] = hadd2(zaccH[nt], hadd2(h01, h23));
        }

        if (it + 1 < NI) {
            float* nbuf = skT[(it + 1) & 1];
            #pragma unroll
            for (int t = 0; t < 4; t++) nbuf[so[t] * 136 + si[t]] = pre[t];
            __syncthreads();
        }
    }

    // reduce over gp lanes (same tg share same j), f16x2
    #pragma unroll
    for (int nt = 0; nt < 8; nt++) {
        uint32_t v = zaccH[nt];
        v = hadd2(v, __shfl_xor_sync(~0u, v, 4));
        v = hadd2(v, __shfl_xor_sync(~0u, v, 8));
        v = hadd2(v, __shfl_xor_sync(~0u, v, 16));
        if (gp == 0) {
            const float2 f = __half22float2(*reinterpret_cast<const __half2*>(&v));
            szw[warp][nt * 8 + 2 * tg]     = f.x;
            szw[warp][nt * 8 + 2 * tg + 1] = f.y;
        }
    }
    __syncthreads();
    if (tid < 64) {
        float z = 0.f;
        #pragma unroll
        for (int w = 0; w < 8; w++) z += szw[w][tid];
        srz[tid] = VSCALE / z;
    }
    __syncthreads();

    // fused v': convert this block's 64-j slice of v
    // 64c x 64j = 4096 elems, 16 per thread; consecutive tid -> consecutive j
    #pragma unroll
    for (int t = 0; t < 16; t++) {
        const int idx = tid + t * 256;
        const int c = idx >> 6, jj = idx & 63;
        g_vp[b][c][j_base + jj] = __float2half(g_v[b][c][j_base + jj] * srz[jj]);
    }
}

// ============================================================================
// outpass: opart[jq][b][c][i] = sum over j-quarter of v'[c,j]*2^(q_j.k_i)
// grid (36, 4, BB), block 256, m=32/warp, ldmatrix.x4, f16 mma. (unchanged)
// ============================================================================
#define SQP 264   // f32 pitch for sq
#define SVP 264   // f16 pitch for sv

__global__ void __launch_bounds__(256, 2) outpass_kernel()
{
    extern __shared__ float sm[];
    float* sq = sm;                              // [8][SQP] f32
    __half* sv = (__half*)(sm + 8 * SQP);        // [64][SVP]
    float* strans = sm;                          // epilogue overlay [64][264]

    const int b = blockIdx.z;
    const int jq = blockIdx.y;
    const int i_base = blockIdx.x * 256;
    const int tid = threadIdx.x;
    const int warp = tid >> 5, lane = tid & 31;
    const int gp = lane >> 2, tg = lane & 3;
    const int iw = warp * 32;

    uint32_t ak[2][4];
    #pragma unroll
    for (int h = 0; h < 2; h++) {
        const int ib = i_base + iw + h * 16;
        ak[h][0] = __float_as_uint(g_k[b][tg][ib + gp]);
        ak[h][1] = __float_as_uint(g_k[b][tg][ib + gp + 8]);
        ak[h][2] = __float_as_uint(g_k[b][tg + 4][ib + gp]);
        ak[h][3] = __float_as_uint(g_k[b][tg + 4][ib + gp + 8]);
    }

    float acc[2][8][4];
    #pragma unroll
    for (int h = 0; h < 2; h++)
        #pragma unroll
        for (int nc = 0; nc < 8; nc++)
            #pragma unroll
            for (int s = 0; s < 4; s++) acc[h][nc][s] = 0.f;

    uint32_t sv_u32;
    asm("{ .reg .u64 t; cvta.to.shared.u64 t, %1; cvt.u32.u64 %0, t; }"
        : "=r"(sv_u32) : "l"(sv));
    const int mrow = ((lane >> 4) << 3) + (lane & 7);
    const int mcol = ((lane >> 3) & 1) * 8;

    uint32_t addrp[4];
    #pragma unroll
    for (int p = 0; p < 4; p++)
        addrp[p] = sv_u32 + (uint32_t)(((p * 16 + mrow) * SVP + mcol) * 2);
    const int sqo0 = tg * SQP + gp;
    const int sqo1 = (tg + 4) * SQP + gp;

    const int j0q = jq * (NN / 4);
    for (int sc = 0; sc < NN / 4 / 256; sc++) {
        const int jb = j0q + sc * 256;
        __syncthreads();
        #pragma unroll
        for (int t = 0; t < 2; t++) {
            const int idx = tid + t * 256;
            const int o = idx >> 6, c4 = idx & 63;
            *(float4*)&sq[o * SQP + c4 * 4] = *(const float4*)&g_q[b][o][jb + c4 * 4];
        }
        #pragma unroll
        for (int t = 0; t < 8; t++) {
            const int idx = tid + t * 256;
            const int row = idx >> 5, q8 = idx & 31;
            *(uint4*)&sv[row * SVP + q8 * 8] = *(const uint4*)&g_vp[b][row][jb + q8 * 8];
        }
        __syncthreads();

        uint32_t pac[2][4];
        {
            const uint32_t B0a = __float_as_uint(sq[sqo0]);
            const uint32_t B1a = __float_as_uint(sq[sqo1]);
            const uint32_t B0b = __float_as_uint(sq[sqo0 + 8]);
            const uint32_t B1b = __float_as_uint(sq[sqo1 + 8]);
            #pragma unroll
            for (int h = 0; h < 2; h++) {
                float eA[4] = {0.f, 0.f, 0.f, 0.f};
                float eB[4] = {0.f, 0.f, 0.f, 0.f};
                mma_tf32(eA, ak[h][0], ak[h][1], ak[h][2], ak[h][3], B0a, B1a);
                mma_tf32(eB, ak[h][0], ak[h][1], ak[h][2], ak[h][3], B0b, B1b);
                pac[h][0] = ex2_h2(pack_f16x2(eA[0], eA[1]));
                pac[h][1] = ex2_h2(pack_f16x2(eA[2], eA[3]));
                pac[h][2] = ex2_h2(pack_f16x2(eB[0], eB[1]));
                pac[h][3] = ex2_h2(pack_f16x2(eB[2], eB[3]));
            }
        }

        #pragma unroll 4
        for (int t = 0; t < 16; t++) {
            const int jj = t * 16;
            uint32_t pan[2][4];
            if (t + 1 < 16) {
                const int jn = jj + 16;
                const uint32_t B0a = __float_as_uint(sq[sqo0 + jn]);
                const uint32_t B1a = __float_as_uint(sq[sqo1 + jn]);
                const uint32_t B0b = __float_as_uint(sq[sqo0 + jn + 8]);
                const uint32_t B1b = __float_as_uint(sq[sqo1 + jn + 8]);
                #pragma unroll
                for (int h = 0; h < 2; h++) {
                    float eA[4] = {0.f, 0.f, 0.f, 0.f};
                    float eB[4] = {0.f, 0.f, 0.f, 0.f};
                    mma_tf32(eA, ak[h][0], ak[h][1], ak[h][2], ak[h][3], B0a, B1a);
                    mma_tf32(eB, ak[h][0], ak[h][1], ak[h][2], ak[h][3], B0b, B1b);
                    pan[h][0] = ex2_h2(pack_f16x2(eA[0], eA[1]));
                    pan[h][1] = ex2_h2(pack_f16x2(eA[2], eA[3]));
                    pan[h][2] = ex2_h2(pack_f16x2(eB[0], eB[1]));
                    pan[h][3] = ex2_h2(pack_f16x2(eB[2], eB[3]));
                }
            }
            #pragma unroll
            for (int p = 0; p < 4; p++) {
                uint32_t r0, r1, r2, r3;
                ldsm_x4(r0, r1, r2, r3, addrp[p] + (uint32_t)(jj * 2));
                #pragma unroll
                for (int h = 0; h < 2; h++) {
                    mma_f16(acc[h][2 * p],     pac[h][0], pac[h][1], pac[h][2], pac[h][3], r0, r1);
                    mma_f16(acc[h][2 * p + 1], pac[h][0], pac[h][1], pac[h][2], pac[h][3], r2, r3);
                }
            }
            if (t + 1 < 16) {
                #pragma unroll
                for (int h = 0; h < 2; h++)
                    #pragma unroll
                    for (int s = 0; s < 4; s++) pac[h][s] = pan[h][s];
            }
        }
    }

    __syncthreads();
    #pragma unroll
    for (int h = 0; h < 2; h++) {
        const int il = iw + h * 16;
        #pragma unroll
        for (int nc = 0; nc < 8; nc++) {
            strans[(nc * 8 + 2 * tg) * 264 + il + gp]         = acc[h][nc][0];
            strans[(nc * 8 + 2 * tg + 1) * 264 + il + gp]     = acc[h][nc][1];
            strans[(nc * 8 + 2 * tg) * 264 + il + gp + 8]     = acc[h][nc][2];
            strans[(nc * 8 + 2 * tg + 1) * 264 + il + gp + 8] = acc[h][nc][3];
        }
    }
    __syncthreads();
    #pragma unroll
    for (int t = 0; t < 16; t++) {
        const int idx = tid + t * 256;
        const int c = idx >> 6, f4 = idx & 63;
        const float4 v = *(const float4*)&strans[c * 264 + f4 * 4];
        *(float4*)&g_opart[jq][b][c][i_base + f4 * 4] = v;
    }
}

// ============================================================================
// combine: out = (gamma/2^12)*(op0+op1+op2+op3) + x  (fixed order)
// ============================================================================
__global__ void __launch_bounds__(256) combine_kernel(
    const float* __restrict__ x,
    const float* __restrict__ gamma,
    float* __restrict__ out)
{
    const int b = blockIdx.y;
    const size_t idx = ((size_t)blockIdx.x * 256 + threadIdx.x) * 4;
    const float gma = gamma[0] * (1.0f / VSCALE);
    const float4 p0 = *(const float4*)&g_opart[0][b][0][idx];
    const float4 p1 = *(const float4*)&g_opart[1][b][0][idx];
    const float4 p2 = *(const float4*)&g_opart[2][b][0][idx];
    const float4 p3 = *(const float4*)&g_opart[3][b][0][idx];
    const float4 xv = *(const float4*)&x[(size_t)b * CC * NN + idx];
    float4 o;
    o.x = gma * ((p0.x + p1.x) + (p2.x + p3.x)) + xv.x;
    o.y = gma * ((p0.y + p1.y) + (p2.y + p3.y)) + xv.y;
    o.z = gma * ((p0.z + p1.z) + (p2.z + p3.z)) + xv.z;
    o.w = gma * ((p0.w + p1.w) + (p2.w + p3.w)) + xv.w;
    *(float4*)&out[(size_t)b * CC * NN + idx] = o;
}

// ============================================================================
extern "C" void kernel_launch(void* const* d_in, const int* in_sizes, int n_in,
                              void* d_out, int out_size)
{
    const float* x     = (const float*)d_in[0];
    const float* wq    = (const float*)d_in[1];
    const float* bq    = (const float*)d_in[2];
    const float* wk    = (const float*)d_in[3];
    const float* bk    = (const float*)d_in[4];
    const float* wv    = (const float*)d_in[5];
    const float* bv    = (const float*)d_in[6];
    const float* gamma = (const float*)d_in[7];
    float* out = (float*)d_out;

    {
        dim3 grid(NN / 256, 5, BB);
        qkv_kernel<<<grid, 128>>>(x, wq, bq, wk, bk, wv, bv);
    }
    {
        dim3 grid(NN / 64, BB);
        zvpass_kernel<<<grid, 256>>>();
    }
    {
        const size_t stage_bytes = 8 * SQP * sizeof(float) + 64 * SVP * sizeof(__half);
        const size_t trans_bytes = 64 * 264 * sizeof(float);
        const size_t shmem = stage_bytes > trans_bytes ? stage_bytes : trans_bytes;
        cudaFuncSetAttribute(outpass_kernel,
                             cudaFuncAttributeMaxDynamicSharedMemorySize, (int)shmem);
        dim3 grid(NN / 256, 4, BB);
        outpass_kernel<<<grid, 256, shmem>>>();
    }
    {
        dim3 grid(CC * NN / 4 / 256, BB);
        combine_kernel<<<grid, 256>>>(x, gamma, out);
    }
}